// round 2
// baseline (speedup 1.0000x reference)
#include <cuda_runtime.h>
#include <cuda_bf16.h>

// ============================================================================
// QuantumAutoEncoder, algebraically collapsed:
//   U_enc, U_dec = exact 64x64 circuit unitaries (built once per launch from
//   the 18 fused RZ*RX gates + per-block RZ/CZ diagonals).
//   latent_k = sum_i z(i,k) |(U_enc h)_i|^2 / ||h||^2
//   recon_k  = sum_i z(i,k) |(U_dec[:,0:3] l)_i|^2 / ||l||^2
//   out      = tanh(W_pre @ recon + b_pre)
// ============================================================================

__device__ __align__(16) float2 g_M[64 * 64];  // g_M[i*64+j] = U_enc[i][j]
__device__ __align__(16) float2 g_D[64 * 3];   // g_D[i*3+p]  = U_dec[i][p], p<3

__device__ __forceinline__ float fast_tanh(float v) {
    float w = fminf(fmaxf(v, -9.0f), 9.0f);
    float e = __expf(2.0f * w);
    return __fdividef(e - 1.0f, e + 1.0f);
}

// ---------------------------------------------------------------------------
// Setup: 17 blocks x 128 threads.
//   blocks 0..15: simulate enc circuit on 4 basis columns each -> g_M
//   block  16   : simulate dec circuit on basis columns 0..2   -> g_D
// Per block b: RX on wires 0..5 (RZ commuted out), then fused diagonal
// (all RZ phases of the block * CZ chain sign). ALL diagonals applied: the
// stored matrices are the exact circuit unitaries.
// ---------------------------------------------------------------------------
__global__ void qae_setup(const float* __restrict__ enc_w,
                          const float* __restrict__ dec_w) {
    __shared__ float sr[4 * 64];
    __shared__ float si[4 * 64];
    const int tid = threadIdx.x;
    const int blk = blockIdx.x;
    const bool isDec = (blk == 16);
    const float* wgt = isDec ? dec_w : enc_w;
    const int ncols = isDec ? 3 : 4;
    const int c0 = isDec ? 0 : blk * 4;

    for (int t = tid; t < ncols * 64; t += 128) {
        int col = t >> 6, a = t & 63;
        sr[t] = (a == c0 + col) ? 1.0f : 0.0f;
        si[t] = 0.0f;
    }
    __syncthreads();

    for (int b = 0; b < 3; b++) {
        // RX gates (wire w acts on bit 5-w; all RX on distinct wires commute)
        for (int w = 0; w < 6; w++) {
            float tx = wgt[(b * 6 + w) * 3 + 0];
            float c = cosf(0.5f * tx);
            float s = sinf(0.5f * tx);
            int m = 1 << (5 - w);
            int np = ncols * 32;
            if (tid < np) {
                int col = tid >> 5;
                int q = tid & 31;
                int low = q & (m - 1);
                int i0 = ((q & ~(m - 1)) << 1) | low;
                int i1 = i0 | m;
                int base = col * 64;
                float a0r = sr[base + i0], a0i = si[base + i0];
                float a1r = sr[base + i1], a1i = si[base + i1];
                // RX: new0 = c*a0 - i*s*a1 ; new1 = -i*s*a0 + c*a1
                sr[base + i0] = fmaf(c, a0r,  s * a1i);
                si[base + i0] = fmaf(c, a0i, -s * a1r);
                sr[base + i1] = fmaf(c, a1r,  s * a0i);
                si[base + i1] = fmaf(c, a1i, -s * a0r);
            }
            __syncthreads();
        }
        // Fused diagonal: RZ phases of all 6 wires + CZ chain sign.
        for (int t = tid; t < ncols * 64; t += 128) {
            int a = t & 63;
            float ang = 0.0f;
#pragma unroll
            for (int k = 0; k < 6; k++) {
                float tz = wgt[(b * 6 + k) * 3 + 1];
                ang += ((a >> (5 - k)) & 1) ? 0.5f * tz : -0.5f * tz;
            }
            float cz = (__popc(a & (a >> 1) & 0x1F) & 1) ? -1.0f : 1.0f;
            float ds, dc;
            sincosf(ang, &ds, &dc);
            dc *= cz; ds *= cz;
            float ar = sr[t], ai = si[t];
            sr[t] = dc * ar - ds * ai;
            si[t] = dc * ai + ds * ar;
        }
        __syncthreads();
    }

    if (!isDec) {
        for (int t = tid; t < 256; t += 128) {
            int col = t >> 6, a = t & 63;
            g_M[a * 64 + (c0 + col)] = make_float2(sr[t], si[t]);
        }
    } else {
        for (int t = tid; t < 192; t += 128) {
            int i = t / 3, p = t % 3;
            g_D[t] = make_float2(sr[p * 64 + i], si[p * 64 + i]);
        }
    }
}

// ---------------------------------------------------------------------------
// Main: one thread per batch item. h[64] in registers, U_enc streamed from
// shared memory (uniform broadcast LDS.128).
// ---------------------------------------------------------------------------
__global__ void __launch_bounds__(256, 2)
qae_main(const float* __restrict__ x, const float* __restrict__ W,
         const float* __restrict__ bvec, float* __restrict__ out, int B) {
    __shared__ float4 sM[2048];   // pairs (Re,Im,Re,Im): sM[i*32 + j/2]
    __shared__ float2 sD[192];
    __shared__ float sW[384];
    __shared__ float sb[64];
    const int tid = threadIdx.x;
    {
        const float4* gm4 = reinterpret_cast<const float4*>(g_M);
        for (int t = tid; t < 2048; t += 256) sM[t] = gm4[t];
        for (int t = tid; t < 384; t += 256) sW[t] = W[t];
        if (tid < 192) sD[tid] = g_D[tid];
        if (tid < 64) sb[tid] = bvec[tid];
    }
    __syncthreads();

    const int item = blockIdx.x * 256 + tid;
    if (item >= B) return;

    const float* xp = x + (size_t)item * 6;
    float x0 = xp[0], x1 = xp[1], x2 = xp[2], x3 = xp[3], x4 = xp[4], x5 = xp[5];

    // h = tanh(W x + b); n1 = ||h||^2
    float h[64];
    float n1 = 0.0f;
#pragma unroll
    for (int j = 0; j < 64; j++) {
        const float* wr = &sW[j * 6];
        float a = sb[j];
        a = fmaf(wr[0], x0, a); a = fmaf(wr[1], x1, a); a = fmaf(wr[2], x2, a);
        a = fmaf(wr[3], x3, a); a = fmaf(wr[4], x4, a); a = fmaf(wr[5], x5, a);
        float t = fast_tanh(a);
        h[j] = t;
        n1 = fmaf(t, t, n1);
    }

    // Encoder: Y = U_enc h; latent_k = sum_i z(i,k) |Y_i|^2 / n1
    float la0 = 0.0f, la1 = 0.0f, la2 = 0.0f;
#pragma unroll 1
    for (int g = 0; g < 16; g++) {
        const float4* r0 = &sM[(g * 4) * 32];
        const float4* r1 = r0 + 32;
        const float4* r2 = r0 + 64;
        const float4* r3 = r0 + 96;
        float ar0 = 0, ai0 = 0, ar1 = 0, ai1 = 0;
        float ar2 = 0, ai2 = 0, ar3 = 0, ai3 = 0;
#pragma unroll
        for (int j2 = 0; j2 < 32; j2++) {
            float h0 = h[2 * j2], h1 = h[2 * j2 + 1];
            float4 m;
            m = r0[j2];
            ar0 = fmaf(m.x, h0, ar0); ai0 = fmaf(m.y, h0, ai0);
            ar0 = fmaf(m.z, h1, ar0); ai0 = fmaf(m.w, h1, ai0);
            m = r1[j2];
            ar1 = fmaf(m.x, h0, ar1); ai1 = fmaf(m.y, h0, ai1);
            ar1 = fmaf(m.z, h1, ar1); ai1 = fmaf(m.w, h1, ai1);
            m = r2[j2];
            ar2 = fmaf(m.x, h0, ar2); ai2 = fmaf(m.y, h0, ai2);
            ar2 = fmaf(m.z, h1, ar2); ai2 = fmaf(m.w, h1, ai2);
            m = r3[j2];
            ar3 = fmaf(m.x, h0, ar3); ai3 = fmaf(m.y, h0, ai3);
            ar3 = fmaf(m.z, h1, ar3); ai3 = fmaf(m.w, h1, ai3);
        }
        float p0 = fmaf(ar0, ar0, ai0 * ai0);
        float p1 = fmaf(ar1, ar1, ai1 * ai1);
        float p2 = fmaf(ar2, ar2, ai2 * ai2);
        float p3 = fmaf(ar3, ar3, ai3 * ai3);
#pragma unroll
        for (int u = 0; u < 4; u++) {
            float p = (u == 0) ? p0 : (u == 1) ? p1 : (u == 2) ? p2 : p3;
            int i = 4 * g + u;
            la0 += (i & 32) ? -p : p;
            la1 += (i & 16) ? -p : p;
            la2 += (i & 8)  ? -p : p;
        }
    }

    float inv1 = 1.0f / n1;
    float l0 = la0 * inv1, l1 = la1 * inv1, l2 = la2 * inv1;

    // Decoder (literal): Y_i = sum_p U_dec[i][p] l_p ; probs normalized by n2
    float n2 = fmaf(l0, l0, fmaf(l1, l1, l2 * l2));
    float inv2 = 1.0f / n2;
    float r[6] = {0, 0, 0, 0, 0, 0};
#pragma unroll
    for (int i = 0; i < 64; i++) {
        float2 d0 = sD[i * 3 + 0];
        float2 d1 = sD[i * 3 + 1];
        float2 d2 = sD[i * 3 + 2];
        float yr = fmaf(d0.x, l0, fmaf(d1.x, l1, d2.x * l2));
        float yi = fmaf(d0.y, l0, fmaf(d1.y, l1, d2.y * l2));
        float p = fmaf(yr, yr, yi * yi);
        r[0] += (i & 32) ? -p : p;
        r[1] += (i & 16) ? -p : p;
        r[2] += (i & 8)  ? -p : p;
        r[3] += (i & 4)  ? -p : p;
        r[4] += (i & 2)  ? -p : p;
        r[5] += (i & 1)  ? -p : p;
    }
#pragma unroll
    for (int k = 0; k < 6; k++) r[k] *= inv2;

    // reconstructed = tanh(W r + b)
    float* op = out + (size_t)item * 64;
#pragma unroll
    for (int j4 = 0; j4 < 16; j4++) {
        float4 o;
        float* oo = reinterpret_cast<float*>(&o);
#pragma unroll
        for (int u = 0; u < 4; u++) {
            int j = j4 * 4 + u;
            const float* wr = &sW[j * 6];
            float a = sb[j];
            a = fmaf(wr[0], r[0], a); a = fmaf(wr[1], r[1], a);
            a = fmaf(wr[2], r[2], a); a = fmaf(wr[3], r[3], a);
            a = fmaf(wr[4], r[4], a); a = fmaf(wr[5], r[5], a);
            oo[u] = fast_tanh(a);
        }
        reinterpret_cast<float4*>(op)[j4] = o;
    }

    float* lp = out + (size_t)B * 64 + (size_t)item * 3;
    lp[0] = l0; lp[1] = l1; lp[2] = l2;
}

extern "C" void kernel_launch(void* const* d_in, const int* in_sizes, int n_in,
                              void* d_out, int out_size) {
    // Size-robust input mapping: x(B*6, largest), W_pre(384), b_pre(64),
    // enc_w(54) then dec_w(54) in order of appearance.
    int xi = 0, maxsz = -1;
    for (int i = 0; i < n_in; i++)
        if (in_sizes[i] > maxsz) { maxsz = in_sizes[i]; xi = i; }
    const float* x = (const float*)d_in[xi];
    const float* W = nullptr;
    const float* b = nullptr;
    const float* ew = nullptr;
    const float* dw = nullptr;
    for (int i = 0; i < n_in; i++) {
        if (i == xi) continue;
        int sz = in_sizes[i];
        if (sz == 384 && !W) W = (const float*)d_in[i];
        else if (sz == 64 && !b) b = (const float*)d_in[i];
        else if (sz == 54) { if (!ew) ew = (const float*)d_in[i]; else dw = (const float*)d_in[i]; }
    }
    int B = in_sizes[xi] / 6;

    qae_setup<<<17, 128>>>(ew, dw);
    qae_main<<<(B + 255) / 256, 256>>>(x, W, b, (float*)d_out, B);
}

// round 3
// speedup vs baseline: 1.0876x; 1.0876x over previous
#include <cuda_runtime.h>
#include <cuda_bf16.h>

// ============================================================================
// QuantumAutoEncoder, algebraically collapsed:
//   U_enc, U_dec = exact 64x64 circuit unitaries (built once per launch).
//   latent_k = sum_i z(i,k) |(U_enc h)_i|^2 / ||h||^2
//   recon_k  = sum_i z(i,k) |(U_dec[:,0:3] l)_i|^2 / ||l||^2
//   out      = tanh(W_pre @ recon + b_pre)
// Main kernel uses packed fp32x2 FMA (FFMA2, PTX fma.rn.f32x2) throughout:
// complex (re,im) pairs and row-pair-packed tanh layers.
// ============================================================================

typedef unsigned long long u64;

__device__ __align__(16) float2 g_M[64 * 64];  // g_M[i*64+j] = U_enc[i][j]
__device__ __align__(16) float2 g_D[64 * 3];   // g_D[i*3+p]  = U_dec[i][p], p<3

__device__ __forceinline__ u64 pack2(float v) {
    u64 r; asm("mov.b64 %0, {%1, %1};" : "=l"(r) : "f"(v)); return r;
}
__device__ __forceinline__ u64 packab(float a, float b) {
    u64 r; asm("mov.b64 %0, {%1, %2};" : "=l"(r) : "f"(a), "f"(b)); return r;
}
__device__ __forceinline__ void unpack2(u64 p, float& a, float& b) {
    asm("mov.b64 {%0, %1}, %2;" : "=f"(a), "=f"(b) : "l"(p));
}
__device__ __forceinline__ void fma2(u64& acc, u64 a, u64 b) {
    asm("fma.rn.f32x2 %0, %1, %2, %0;" : "+l"(acc) : "l"(a), "l"(b));
}

__device__ __forceinline__ float fast_tanh(float v) {
    float w = fminf(fmaxf(v, -9.0f), 9.0f);
    float e = __expf(2.0f * w);
    return __fdividef(e - 1.0f, e + 1.0f);
}

// ---------------------------------------------------------------------------
// Setup: 17 blocks x 128 threads (blocks 0..15 -> g_M, block 16 -> g_D).
// Per circuit block b: RX on wires 0..5, then fused diagonal (RZ phases + CZ).
// ---------------------------------------------------------------------------
__global__ void qae_setup(const float* __restrict__ enc_w,
                          const float* __restrict__ dec_w) {
    __shared__ float sr[4 * 64];
    __shared__ float si[4 * 64];
    const int tid = threadIdx.x;
    const int blk = blockIdx.x;
    const bool isDec = (blk == 16);
    const float* wgt = isDec ? dec_w : enc_w;
    const int ncols = isDec ? 3 : 4;
    const int c0 = isDec ? 0 : blk * 4;

    for (int t = tid; t < ncols * 64; t += 128) {
        int col = t >> 6, a = t & 63;
        sr[t] = (a == c0 + col) ? 1.0f : 0.0f;
        si[t] = 0.0f;
    }
    __syncthreads();

    for (int b = 0; b < 3; b++) {
        for (int w = 0; w < 6; w++) {
            float tx = wgt[(b * 6 + w) * 3 + 0];
            float c = cosf(0.5f * tx);
            float s = sinf(0.5f * tx);
            int m = 1 << (5 - w);
            int np = ncols * 32;
            if (tid < np) {
                int col = tid >> 5;
                int q = tid & 31;
                int low = q & (m - 1);
                int i0 = ((q & ~(m - 1)) << 1) | low;
                int i1 = i0 | m;
                int base = col * 64;
                float a0r = sr[base + i0], a0i = si[base + i0];
                float a1r = sr[base + i1], a1i = si[base + i1];
                sr[base + i0] = fmaf(c, a0r,  s * a1i);
                si[base + i0] = fmaf(c, a0i, -s * a1r);
                sr[base + i1] = fmaf(c, a1r,  s * a0i);
                si[base + i1] = fmaf(c, a1i, -s * a0r);
            }
            __syncthreads();
        }
        for (int t = tid; t < ncols * 64; t += 128) {
            int a = t & 63;
            float ang = 0.0f;
#pragma unroll
            for (int k = 0; k < 6; k++) {
                float tz = wgt[(b * 6 + k) * 3 + 1];
                ang += ((a >> (5 - k)) & 1) ? 0.5f * tz : -0.5f * tz;
            }
            float cz = (__popc(a & (a >> 1) & 0x1F) & 1) ? -1.0f : 1.0f;
            float ds, dc;
            sincosf(ang, &ds, &dc);
            dc *= cz; ds *= cz;
            float ar = sr[t], ai = si[t];
            sr[t] = dc * ar - ds * ai;
            si[t] = dc * ai + ds * ar;
        }
        __syncthreads();
    }

    if (!isDec) {
        for (int t = tid; t < 256; t += 128) {
            int col = t >> 6, a = t & 63;
            g_M[a * 64 + (c0 + col)] = make_float2(sr[t], si[t]);
        }
    } else {
        for (int t = tid; t < 192; t += 128) {
            int i = t / 3, p = t % 3;
            g_D[t] = make_float2(sr[p * 64 + i], si[p * 64 + i]);
        }
    }
}

// ---------------------------------------------------------------------------
// Main: one thread per batch item. h[64] in regs, U_enc streamed from smem
// via broadcast LDS.128, all heavy math as packed f32x2 FMA.
// ---------------------------------------------------------------------------
__global__ void __launch_bounds__(256, 2)
qae_main(const float* __restrict__ x, const float* __restrict__ W,
         const float* __restrict__ bvec, float* __restrict__ out, int B) {
    __shared__ ulonglong2 sM2[2048];  // row i at [i*32 .. i*32+31], 2 cols per entry
    __shared__ u64 sD2[192];          // (re,im) per (i,p)
    __shared__ u64 sWp[192];          // sWp[k*32+j] = (W[2j][k], W[2j+1][k])
    __shared__ u64 sb2[32];           // (b[2j], b[2j+1])
    const int tid = threadIdx.x;
    {
        const ulonglong2* gm = reinterpret_cast<const ulonglong2*>(g_M);
        for (int t = tid; t < 2048; t += 256) sM2[t] = gm[t];
        const u64* gd = reinterpret_cast<const u64*>(g_D);
        if (tid < 192) {
            sD2[tid] = gd[tid];
            int k = tid >> 5, j = tid & 31;
            sWp[tid] = packab(W[(2 * j) * 6 + k], W[(2 * j + 1) * 6 + k]);
        }
        if (tid < 32) sb2[tid] = packab(bvec[2 * tid], bvec[2 * tid + 1]);
    }
    __syncthreads();

    const int item = blockIdx.x * 256 + tid;
    if (item >= B) return;

    const float* xp = x + (size_t)item * 6;
    u64 x2[6];
#pragma unroll
    for (int k = 0; k < 6; k++) x2[k] = pack2(xp[k]);

    // h = tanh(W x + b) row-pair packed; n1 = ||h||^2
    float h[64];
    float n1 = 0.0f;
#pragma unroll
    for (int j = 0; j < 32; j++) {
        u64 a = sb2[j];
#pragma unroll
        for (int k = 0; k < 6; k++) fma2(a, sWp[k * 32 + j], x2[k]);
        float v0, v1;
        unpack2(a, v0, v1);
        float t0 = fast_tanh(v0), t1 = fast_tanh(v1);
        h[2 * j] = t0; h[2 * j + 1] = t1;
        n1 = fmaf(t0, t0, n1);
        n1 = fmaf(t1, t1, n1);
    }

    // Encoder: Y = U_enc h, 8 rows per group, packed complex accumulators.
    float la0 = 0.0f, la1 = 0.0f, la2 = 0.0f;
#pragma unroll 1
    for (int g = 0; g < 8; g++) {
        const ulonglong2* base = &sM2[g * 8 * 32];
        u64 acc[8];
#pragma unroll
        for (int u = 0; u < 8; u++) acc[u] = 0ull;
#pragma unroll 8
        for (int j2 = 0; j2 < 32; j2++) {
            u64 ha = pack2(h[2 * j2]);
            u64 hb = pack2(h[2 * j2 + 1]);
#pragma unroll
            for (int u = 0; u < 8; u++) {
                ulonglong2 m = base[u * 32 + j2];
                fma2(acc[u], m.x, ha);
                fma2(acc[u], m.y, hb);
            }
        }
        float ps = 0.0f;
#pragma unroll
        for (int u = 0; u < 8; u++) {
            float ar, ai;
            unpack2(acc[u], ar, ai);
            ps += fmaf(ar, ar, ai * ai);
        }
        // rows i = 8g+u share bits 5..3 = g: z-signs constant per group
        la0 += (g & 4) ? -ps : ps;
        la1 += (g & 2) ? -ps : ps;
        la2 += (g & 1) ? -ps : ps;
    }

    float inv1 = 1.0f / n1;
    float l0 = la0 * inv1, l1 = la1 * inv1, l2 = la2 * inv1;

    // Decoder: Y_i = sum_p U_dec[i][p] l_p (packed), z-sign reductions
    float n2 = fmaf(l0, l0, fmaf(l1, l1, l2 * l2));
    float inv2 = 1.0f / n2;
    u64 L0 = pack2(l0), L1 = pack2(l1), L2 = pack2(l2);
    float r[6] = {0, 0, 0, 0, 0, 0};
#pragma unroll 8
    for (int i = 0; i < 64; i++) {
        u64 y = 0ull;
        fma2(y, sD2[i * 3 + 0], L0);
        fma2(y, sD2[i * 3 + 1], L1);
        fma2(y, sD2[i * 3 + 2], L2);
        float yr, yi;
        unpack2(y, yr, yi);
        float p = fmaf(yr, yr, yi * yi);
        r[0] += (i & 32) ? -p : p;
        r[1] += (i & 16) ? -p : p;
        r[2] += (i & 8)  ? -p : p;
        r[3] += (i & 4)  ? -p : p;
        r[4] += (i & 2)  ? -p : p;
        r[5] += (i & 1)  ? -p : p;
    }
    u64 r2[6];
#pragma unroll
    for (int k = 0; k < 6; k++) r2[k] = pack2(r[k] * inv2);

    // reconstructed = tanh(W r + b), row-pair packed
    float o[64];
#pragma unroll
    for (int j = 0; j < 32; j++) {
        u64 a = sb2[j];
#pragma unroll
        for (int k = 0; k < 6; k++) fma2(a, sWp[k * 32 + j], r2[k]);
        float v0, v1;
        unpack2(a, v0, v1);
        o[2 * j] = fast_tanh(v0);
        o[2 * j + 1] = fast_tanh(v1);
    }
    float* op = out + (size_t)item * 64;
#pragma unroll
    for (int j4 = 0; j4 < 16; j4++)
        reinterpret_cast<float4*>(op)[j4] =
            make_float4(o[4 * j4], o[4 * j4 + 1], o[4 * j4 + 2], o[4 * j4 + 3]);

    float* lp = out + (size_t)B * 64 + (size_t)item * 3;
    lp[0] = l0; lp[1] = l1; lp[2] = l2;
}

extern "C" void kernel_launch(void* const* d_in, const int* in_sizes, int n_in,
                              void* d_out, int out_size) {
    // Size-robust input mapping: x(B*6, largest), W_pre(384), b_pre(64),
    // enc_w(54) then dec_w(54) in order of appearance.
    int xi = 0, maxsz = -1;
    for (int i = 0; i < n_in; i++)
        if (in_sizes[i] > maxsz) { maxsz = in_sizes[i]; xi = i; }
    const float* x = (const float*)d_in[xi];
    const float* W = nullptr;
    const float* b = nullptr;
    const float* ew = nullptr;
    const float* dw = nullptr;
    for (int i = 0; i < n_in; i++) {
        if (i == xi) continue;
        int sz = in_sizes[i];
        if (sz == 384 && !W) W = (const float*)d_in[i];
        else if (sz == 64 && !b) b = (const float*)d_in[i];
        else if (sz == 54) { if (!ew) ew = (const float*)d_in[i]; else dw = (const float*)d_in[i]; }
    }
    int B = in_sizes[xi] / 6;

    qae_setup<<<17, 128>>>(ew, dw);
    qae_main<<<(B + 255) / 256, 256>>>(x, W, b, (float*)d_out, B);
}

// round 4
// speedup vs baseline: 2.4803x; 2.2805x over previous
#include <cuda_runtime.h>
#include <cuda_bf16.h>

// ============================================================================
// QuantumAutoEncoder, tensor-core formulation.
//   Setup builds U_enc as split-bf16 (hi+lo) in N-major layout (N=128 real
//   rows: col 2i = Re U[i][:], col 2i+1 = Im U[i][:]) and U_dec cols 0..2.
//   Main kernel per CTA (128 items):
//     phase1: h = tanh(W x + b) -> split bf16 into smem A tile (padded rows)
//     GEMM:   Y = h @ U^T via mma.sync m16n8k16 bf16, 4-pass split
//             epilogue in fragments: p = yre^2+yim^2, signed reduce -> latent
//     phase2: decoder quad forms + final tanh layer, stores.
// ============================================================================

typedef unsigned int u32;
typedef unsigned long long u64;

__device__ __align__(16) float2 g_D[64 * 3];            // U_dec[i][p]
__device__ __align__(4) unsigned short g_ubh[128 * 64]; // Ut hi bf16 [n][k]
__device__ __align__(4) unsigned short g_ubl[128 * 64]; // Ut lo bf16 [n][k]

__device__ __forceinline__ u64 pack2(float v) {
    u64 r; asm("mov.b64 %0, {%1, %1};" : "=l"(r) : "f"(v)); return r;
}
__device__ __forceinline__ u64 packab(float a, float b) {
    u64 r; asm("mov.b64 %0, {%1, %2};" : "=l"(r) : "f"(a), "f"(b)); return r;
}
__device__ __forceinline__ void unpack2(u64 p, float& a, float& b) {
    asm("mov.b64 {%0, %1}, %2;" : "=f"(a), "=f"(b) : "l"(p));
}
__device__ __forceinline__ void fma2(u64& acc, u64 a, u64 b) {
    asm("fma.rn.f32x2 %0, %1, %2, %0;" : "+l"(acc) : "l"(a), "l"(b));
}

__device__ __forceinline__ float fast_tanh(float v) {
    float w = fminf(fmaxf(v, -9.0f), 9.0f);
    float e = __expf(2.0f * w);
    return __fdividef(e - 1.0f, e + 1.0f);
}

__device__ __forceinline__ u32 pack_bf2(float a, float b) {
    __nv_bfloat16 ba = __float2bfloat16(a);
    __nv_bfloat16 bb = __float2bfloat16(b);
    u32 ra = *reinterpret_cast<unsigned short*>(&ba);
    u32 rb = *reinterpret_cast<unsigned short*>(&bb);
    return (rb << 16) | ra;
}

__device__ __forceinline__ void mma_bf16(float c[4], u32 a0, u32 a1, u32 a2,
                                         u32 a3, u32 b0, u32 b1) {
    asm("mma.sync.aligned.m16n8k16.row.col.f32.bf16.bf16.f32 "
        "{%0,%1,%2,%3}, {%4,%5,%6,%7}, {%8,%9}, {%0,%1,%2,%3};"
        : "+f"(c[0]), "+f"(c[1]), "+f"(c[2]), "+f"(c[3])
        : "r"(a0), "r"(a1), "r"(a2), "r"(a3), "r"(b0), "r"(b1));
}

// ---------------------------------------------------------------------------
// Setup: 17 blocks x 128 threads (0..15 -> U_enc columns, 16 -> U_dec cols 0..2)
// ---------------------------------------------------------------------------
__global__ void qae_setup(const float* __restrict__ enc_w,
                          const float* __restrict__ dec_w) {
    __shared__ float sr[4 * 64];
    __shared__ float si[4 * 64];
    const int tid = threadIdx.x;
    const int blk = blockIdx.x;
    const bool isDec = (blk == 16);
    const float* wgt = isDec ? dec_w : enc_w;
    const int ncols = isDec ? 3 : 4;
    const int c0 = isDec ? 0 : blk * 4;

    for (int t = tid; t < ncols * 64; t += 128) {
        int col = t >> 6, a = t & 63;
        sr[t] = (a == c0 + col) ? 1.0f : 0.0f;
        si[t] = 0.0f;
    }
    __syncthreads();

    for (int b = 0; b < 3; b++) {
        for (int w = 0; w < 6; w++) {
            float tx = wgt[(b * 6 + w) * 3 + 0];
            float c = cosf(0.5f * tx);
            float s = sinf(0.5f * tx);
            int m = 1 << (5 - w);
            int np = ncols * 32;
            if (tid < np) {
                int col = tid >> 5;
                int q = tid & 31;
                int low = q & (m - 1);
                int i0 = ((q & ~(m - 1)) << 1) | low;
                int i1 = i0 | m;
                int base = col * 64;
                float a0r = sr[base + i0], a0i = si[base + i0];
                float a1r = sr[base + i1], a1i = si[base + i1];
                sr[base + i0] = fmaf(c, a0r,  s * a1i);
                si[base + i0] = fmaf(c, a0i, -s * a1r);
                sr[base + i1] = fmaf(c, a1r,  s * a0i);
                si[base + i1] = fmaf(c, a1i, -s * a0r);
            }
            __syncthreads();
        }
        for (int t = tid; t < ncols * 64; t += 128) {
            int a = t & 63;
            float ang = 0.0f;
#pragma unroll
            for (int k = 0; k < 6; k++) {
                float tz = wgt[(b * 6 + k) * 3 + 1];
                ang += ((a >> (5 - k)) & 1) ? 0.5f * tz : -0.5f * tz;
            }
            float cz = (__popc(a & (a >> 1) & 0x1F) & 1) ? -1.0f : 1.0f;
            float ds, dc;
            sincosf(ang, &ds, &dc);
            dc *= cz; ds *= cz;
            float ar = sr[t], ai = si[t];
            sr[t] = dc * ar - ds * ai;
            si[t] = dc * ai + ds * ar;
        }
        __syncthreads();
    }

    if (!isDec) {
        // write Ut[n][k]: n = 2a (Re), 2a+1 (Im); k = column index j = c0+col
        for (int t = tid; t < 256; t += 128) {
            int col = t >> 6, a = t & 63;
            int j = c0 + col;
            float vr = sr[t], vi = si[t];
            __nv_bfloat16 hr = __float2bfloat16(vr);
            float lr = vr - __bfloat162float(hr);
            __nv_bfloat16 lrb = __float2bfloat16(lr);
            __nv_bfloat16 hi2 = __float2bfloat16(vi);
            float li = vi - __bfloat162float(hi2);
            __nv_bfloat16 lib = __float2bfloat16(li);
            g_ubh[(2 * a) * 64 + j]     = *reinterpret_cast<unsigned short*>(&hr);
            g_ubl[(2 * a) * 64 + j]     = *reinterpret_cast<unsigned short*>(&lrb);
            g_ubh[(2 * a + 1) * 64 + j] = *reinterpret_cast<unsigned short*>(&hi2);
            g_ubl[(2 * a + 1) * 64 + j] = *reinterpret_cast<unsigned short*>(&lib);
        }
    } else {
        for (int t = tid; t < 192; t += 128) {
            int i = t / 3, p = t % 3;
            g_D[t] = make_float2(sr[p * 64 + i], si[p * 64 + i]);
        }
    }
}

// ---------------------------------------------------------------------------
// Main kernel: 256 threads, 128 items per CTA.
// Dynamic smem layout (bytes):
//   [0,     18432)  sAh  : u32[128*36]  (A hi, padded row stride 36 words)
//                   sRp  : float[2*128*6] (phase2 alias, after GEMM done)
//   [18432, 36864)  sAl  : u32[128*36]  (A lo)
//   [36864, 49152)  sLa  : float[8*128*3] (per-warp latent partials)
//                   sx   : float[768]   (phase1 alias)
//   [49152, 50176)  n1s  : float[2*128]
//   [50176, 51712)  sW   : float[384]   (unused slack kept for alignment)
//   [51712, 53248)  sWp  : u64[192]
//   [53248, 53504)  sb2  : u64[32]
//   [53504, 55040)  sD   : u64[192]
// ---------------------------------------------------------------------------
#define SMEM_BYTES 55040

__global__ void __launch_bounds__(256, 2)
qae_main(const float* __restrict__ x, const float* __restrict__ W,
         const float* __restrict__ bvec, float* __restrict__ out, int B) {
    extern __shared__ char smem[];
    u32*   sAh = reinterpret_cast<u32*>(smem);
    u32*   sAl = reinterpret_cast<u32*>(smem + 18432);
    float* sLa = reinterpret_cast<float*>(smem + 36864);
    float* sx  = reinterpret_cast<float*>(smem + 36864);  // alias (phase1 only)
    float* n1s = reinterpret_cast<float*>(smem + 49152);
    u64*   sWp = reinterpret_cast<u64*>(smem + 51712);
    u64*   sb2 = reinterpret_cast<u64*>(smem + 53248);
    u64*   sD  = reinterpret_cast<u64*>(smem + 53504);
    float* sRp = reinterpret_cast<float*>(smem);           // alias (phase2 only)

    const int tid = threadIdx.x;
    const u64* gD64 = reinterpret_cast<const u64*>(g_D);

    if (tid < 192) {
        int k = tid >> 5, jp = tid & 31;
        sWp[tid] = packab(W[(2 * jp) * 6 + k], W[(2 * jp + 1) * 6 + k]);
        sD[tid] = gD64[tid];
    }
    if (tid < 32) sb2[tid] = packab(bvec[2 * tid], bvec[2 * tid + 1]);
    {
        int base = blockIdx.x * 768;
        for (int t = tid; t < 768; t += 256) {
            int gi = base + t;
            sx[t] = (gi < B * 6) ? x[gi] : 0.0f;
        }
    }
    __syncthreads();

    const int item = tid & 127;
    const int half = tid >> 7;
    const int gitem = blockIdx.x * 128 + item;

    // ---- Phase 1: h = tanh(W x + b), split to bf16 hi/lo in smem A tile ----
    {
        u64 xv[6];
#pragma unroll
        for (int k = 0; k < 6; k++) xv[k] = pack2(sx[item * 6 + k]);
        float n1p = 0.0f;
#pragma unroll
        for (int jj = 0; jj < 16; jj++) {
            int jp = half * 16 + jj;
            u64 a = sb2[jp];
#pragma unroll
            for (int k = 0; k < 6; k++) fma2(a, sWp[k * 32 + jp], xv[k]);
            float v0, v1;
            unpack2(a, v0, v1);
            float t0 = fast_tanh(v0), t1 = fast_tanh(v1);
            n1p = fmaf(t0, t0, n1p);
            n1p = fmaf(t1, t1, n1p);
            __nv_bfloat16 b0 = __float2bfloat16(t0);
            __nv_bfloat16 b1 = __float2bfloat16(t1);
            float l0f = t0 - __bfloat162float(b0);
            float l1f = t1 - __bfloat162float(b1);
            u32 rb0 = *reinterpret_cast<unsigned short*>(&b0);
            u32 rb1 = *reinterpret_cast<unsigned short*>(&b1);
            sAh[item * 36 + jp] = (rb1 << 16) | rb0;
            sAl[item * 36 + jp] = pack_bf2(l0f, l1f);
        }
        n1s[half * 128 + item] = n1p;
    }
    __syncthreads();

    // ---- GEMM: Y = A(128x64) @ B(64x128), 4-pass split bf16 ----
    {
        const int w = tid >> 5;
        const int lane = tid & 31;
        const int g = lane >> 2;
        const int q = lane & 3;

        // persistent B fragments (loaded once from global; L2-resident)
        u32 bh[2][4][2], bl[2][4][2];
        const u32* ubh32 = reinterpret_cast<const u32*>(g_ubh);
        const u32* ubl32 = reinterpret_cast<const u32*>(g_ubl);
#pragma unroll
        for (int nt = 0; nt < 2; nt++) {
            int n = w * 16 + nt * 8 + g;
#pragma unroll
            for (int ks = 0; ks < 4; ks++) {
                int wb = n * 32 + ks * 8 + q;
                bh[nt][ks][0] = ubh32[wb];
                bh[nt][ks][1] = ubh32[wb + 4];
                bl[nt][ks][0] = ubl32[wb];
                bl[nt][ks][1] = ubl32[wb + 4];
            }
        }

#pragma unroll 1
        for (int mt = 0; mt < 8; mt++) {
            float c[2][4];
#pragma unroll
            for (int nt = 0; nt < 2; nt++)
#pragma unroll
                for (int u = 0; u < 4; u++) c[nt][u] = 0.0f;

            int rowA = mt * 16 + g;
#pragma unroll
            for (int ks = 0; ks < 4; ks++) {
                int wa = rowA * 36 + ks * 8 + q;
                u32 ah0 = sAh[wa], ah1 = sAh[wa + 288];
                u32 ah2 = sAh[wa + 4], ah3 = sAh[wa + 292];
                u32 al0 = sAl[wa], al1 = sAl[wa + 288];
                u32 al2 = sAl[wa + 4], al3 = sAl[wa + 292];
#pragma unroll
                for (int nt = 0; nt < 2; nt++) {
                    mma_bf16(c[nt], ah0, ah1, ah2, ah3, bh[nt][ks][0], bh[nt][ks][1]);
                    mma_bf16(c[nt], ah0, ah1, ah2, ah3, bl[nt][ks][0], bl[nt][ks][1]);
                    mma_bf16(c[nt], al0, al1, al2, al3, bh[nt][ks][0], bh[nt][ks][1]);
                    mma_bf16(c[nt], al0, al1, al2, al3, bl[nt][ks][0], bl[nt][ks][1]);
                }
            }

            // epilogue: p = yre^2 + yim^2 per (row, complex i), signed sums
            float e[6] = {0, 0, 0, 0, 0, 0};
#pragma unroll
            for (int nt = 0; nt < 2; nt++) {
                float pl = fmaf(c[nt][0], c[nt][0], c[nt][1] * c[nt][1]);
                float ph = fmaf(c[nt][2], c[nt][2], c[nt][3] * c[nt][3]);
                int i = w * 8 + nt * 4 + q;
                float s0 = (i & 32) ? -1.0f : 1.0f;
                float s1 = (i & 16) ? -1.0f : 1.0f;
                float s2 = (i & 8)  ? -1.0f : 1.0f;
                e[0] = fmaf(s0, pl, e[0]); e[1] = fmaf(s1, pl, e[1]);
                e[2] = fmaf(s2, pl, e[2]);
                e[3] = fmaf(s0, ph, e[3]); e[4] = fmaf(s1, ph, e[4]);
                e[5] = fmaf(s2, ph, e[5]);
            }
#pragma unroll
            for (int k = 0; k < 6; k++) {
                e[k] += __shfl_xor_sync(0xffffffffu, e[k], 1);
                e[k] += __shfl_xor_sync(0xffffffffu, e[k], 2);
            }
            if (q == 0) {
                float* d0 = &sLa[(w * 128 + mt * 16 + g) * 3];
                d0[0] = e[0]; d0[1] = e[1]; d0[2] = e[2];
                float* d1 = &sLa[(w * 128 + mt * 16 + g + 8) * 3];
                d1[0] = e[3]; d1[1] = e[4]; d1[2] = e[5];
            }
        }
    }
    __syncthreads();

    // ---- Phase 2: latent, decoder, final layer ----
    float la0 = 0, la1 = 0, la2 = 0;
#pragma unroll
    for (int ww = 0; ww < 8; ww++) {
        const float* p = &sLa[(ww * 128 + item) * 3];
        la0 += p[0]; la1 += p[1]; la2 += p[2];
    }
    float n1 = n1s[item] + n1s[128 + item];
    float inv1 = 1.0f / n1;
    float l0 = la0 * inv1, l1 = la1 * inv1, l2 = la2 * inv1;
    const bool live = (gitem < B);
    if (live && half == 0) {
        float* lp = out + (size_t)B * 64 + (size_t)gitem * 3;
        lp[0] = l0; lp[1] = l1; lp[2] = l2;
    }

    // decoder partial over this thread's 32 basis states
    float r[6] = {0, 0, 0, 0, 0, 0};
    {
        u64 L0 = pack2(l0), L1 = pack2(l1), L2 = pack2(l2);
        float sH = half ? -1.0f : 1.0f;  // bit5 of i = half
#pragma unroll 8
        for (int ii = 0; ii < 32; ii++) {
            int i = half * 32 + ii;
            u64 y = 0ull;
            fma2(y, sD[i * 3 + 0], L0);
            fma2(y, sD[i * 3 + 1], L1);
            fma2(y, sD[i * 3 + 2], L2);
            float yr, yi;
            unpack2(y, yr, yi);
            float p = fmaf(yr, yr, yi * yi);
            r[0] = fmaf(sH, p, r[0]);
            r[1] += (ii & 16) ? -p : p;
            r[2] += (ii & 8)  ? -p : p;
            r[3] += (ii & 4)  ? -p : p;
            r[4] += (ii & 2)  ? -p : p;
            r[5] += (ii & 1)  ? -p : p;
        }
    }
    {
        float* rp = &sRp[(half * 128 + item) * 6];
#pragma unroll
        for (int k = 0; k < 6; k++) rp[k] = r[k];
    }
    __syncthreads();

    {
        const float* ra = &sRp[item * 6];
        const float* rb = &sRp[(128 + item) * 6];
        float n2 = fmaf(l0, l0, fmaf(l1, l1, l2 * l2));
        float inv2 = 1.0f / n2;
        u64 r2[6];
#pragma unroll
        for (int k = 0; k < 6; k++) r2[k] = pack2((ra[k] + rb[k]) * inv2);

        if (live) {
            float* op = out + (size_t)gitem * 64 + half * 32;
#pragma unroll
            for (int jj = 0; jj < 16; jj += 2) {
                int jp = half * 16 + jj;
                u64 a0 = sb2[jp];
                u64 a1 = sb2[jp + 1];
#pragma unroll
                for (int k = 0; k < 6; k++) {
                    fma2(a0, sWp[k * 32 + jp], r2[k]);
                    fma2(a1, sWp[k * 32 + jp + 1], r2[k]);
                }
                float v0, v1, v2, v3;
                unpack2(a0, v0, v1);
                unpack2(a1, v2, v3);
                float4 o = make_float4(fast_tanh(v0), fast_tanh(v1),
                                       fast_tanh(v2), fast_tanh(v3));
                reinterpret_cast<float4*>(op)[jj >> 1] = o;
            }
        }
    }
}

extern "C" void kernel_launch(void* const* d_in, const int* in_sizes, int n_in,
                              void* d_out, int out_size) {
    // Size-robust input mapping: x(B*6, largest), W_pre(384), b_pre(64),
    // enc_w(54) then dec_w(54) in order of appearance.
    int xi = 0, maxsz = -1;
    for (int i = 0; i < n_in; i++)
        if (in_sizes[i] > maxsz) { maxsz = in_sizes[i]; xi = i; }
    const float* x = (const float*)d_in[xi];
    const float* W = nullptr;
    const float* b = nullptr;
    const float* ew = nullptr;
    const float* dw = nullptr;
    for (int i = 0; i < n_in; i++) {
        if (i == xi) continue;
        int sz = in_sizes[i];
        if (sz == 384 && !W) W = (const float*)d_in[i];
        else if (sz == 64 && !b) b = (const float*)d_in[i];
        else if (sz == 54) { if (!ew) ew = (const float*)d_in[i]; else dw = (const float*)d_in[i]; }
    }
    int B = in_sizes[xi] / 6;

    cudaFuncSetAttribute(qae_main, cudaFuncAttributeMaxDynamicSharedMemorySize,
                         SMEM_BYTES);

    qae_setup<<<17, 128>>>(ew, dw);
    qae_main<<<(B + 127) / 128, 256, SMEM_BYTES>>>(x, W, b, (float*)d_out, B);
}